// round 1
// baseline (speedup 1.0000x reference)
#include <cuda_runtime.h>
#include <cuda_bf16.h>
#include <math.h>

// Problem shape (fixed by the dataset)
#define B  32
#define Ls 512
#define D  768
#define Kp 8192
#define M  (B * Ls)          // 16384 rows

// ---------------- scratch (device globals: allocation-free) ----------------
__device__ float g_logits[(size_t)M * Kp];   // 512 MB fp32 logits
__device__ float g_c[M];                     // per-row  m + log(sum exp)

// ---------------- GEMM: logits[m][k] = dot(Q[m], P[k]) / temp --------------
// Block tile 128x128, BK=16, 256 threads, 8x8 per thread.
#define BM 128
#define BN 128
#define BK 16
#define PAD 4

__global__ __launch_bounds__(256, 2)
void gemm_logits(const float* __restrict__ Q, const float* __restrict__ P,
                 const float* __restrict__ temp)
{
    __shared__ float As[BK][BM + PAD];
    __shared__ float Bs[BK][BN + PAD];

    const int tid = threadIdx.x;
    const int tx  = tid & 15;          // 0..15  -> N direction
    const int ty  = tid >> 4;          // 0..15  -> M direction
    const int m0  = blockIdx.y * BM;
    const int n0  = blockIdx.x * BN;

    float acc[8][8];
#pragma unroll
    for (int i = 0; i < 8; i++)
#pragma unroll
        for (int j = 0; j < 8; j++) acc[i][j] = 0.f;

    const float invT = 1.0f / temp[0];

    for (int kd0 = 0; kd0 < D; kd0 += BK) {
        // load A tile (128 rows x 16 cols) and B tile, transposed into [k][row]
#pragma unroll
        for (int t = 0; t < 2; t++) {
            int i   = tid + t * 256;       // 0..511
            int row = i >> 2;              // 0..127
            int c4  = (i & 3) * 4;         // 0,4,8,12
            float4 va = *reinterpret_cast<const float4*>(&Q[(size_t)(m0 + row) * D + kd0 + c4]);
            As[c4 + 0][row] = va.x;
            As[c4 + 1][row] = va.y;
            As[c4 + 2][row] = va.z;
            As[c4 + 3][row] = va.w;
            float4 vb = *reinterpret_cast<const float4*>(&P[(size_t)(n0 + row) * D + kd0 + c4]);
            Bs[c4 + 0][row] = vb.x;
            Bs[c4 + 1][row] = vb.y;
            Bs[c4 + 2][row] = vb.z;
            Bs[c4 + 3][row] = vb.w;
        }
        __syncthreads();

#pragma unroll
        for (int k = 0; k < BK; k++) {
            float a[8], b[8];
            *reinterpret_cast<float4*>(&a[0]) = *reinterpret_cast<const float4*>(&As[k][ty * 8 + 0]);
            *reinterpret_cast<float4*>(&a[4]) = *reinterpret_cast<const float4*>(&As[k][ty * 8 + 4]);
            *reinterpret_cast<float4*>(&b[0]) = *reinterpret_cast<const float4*>(&Bs[k][tx * 8 + 0]);
            *reinterpret_cast<float4*>(&b[4]) = *reinterpret_cast<const float4*>(&Bs[k][tx * 8 + 4]);
#pragma unroll
            for (int i = 0; i < 8; i++)
#pragma unroll
                for (int j = 0; j < 8; j++) acc[i][j] = fmaf(a[i], b[j], acc[i][j]);
        }
        __syncthreads();
    }

    // write back (scaled by 1/temp)
#pragma unroll
    for (int i = 0; i < 8; i++) {
        size_t o = (size_t)(m0 + ty * 8 + i) * Kp + n0 + tx * 8;
        float4 w0 = make_float4(acc[i][0] * invT, acc[i][1] * invT, acc[i][2] * invT, acc[i][3] * invT);
        float4 w1 = make_float4(acc[i][4] * invT, acc[i][5] * invT, acc[i][6] * invT, acc[i][7] * invT);
        *reinterpret_cast<float4*>(&g_logits[o + 0]) = w0;
        *reinterpret_cast<float4*>(&g_logits[o + 4]) = w1;
    }
}

// ---------------- per-row softmax stats: c = m + log(sum exp) --------------
__device__ __forceinline__ float warpMax(float v) {
#pragma unroll
    for (int o = 16; o; o >>= 1) v = fmaxf(v, __shfl_xor_sync(0xffffffffu, v, o));
    return v;
}
__device__ __forceinline__ float warpSum(float v) {
#pragma unroll
    for (int o = 16; o; o >>= 1) v += __shfl_xor_sync(0xffffffffu, v, o);
    return v;
}

__global__ __launch_bounds__(256)
void row_stats()
{
    const int row = blockIdx.x;
    const float* Lr = g_logits + (size_t)row * Kp;
    const int tid = threadIdx.x;
    __shared__ float sh[8];
    __shared__ float bc;

    float m = -INFINITY;
    for (int i = tid; i < Kp; i += 256) m = fmaxf(m, Lr[i]);
    m = warpMax(m);
    if ((tid & 31) == 0) sh[tid >> 5] = m;
    __syncthreads();
    if (tid == 0) {
        float t = sh[0];
#pragma unroll
        for (int w = 1; w < 8; w++) t = fmaxf(t, sh[w]);
        bc = t;
    }
    __syncthreads();
    m = bc;

    float s = 0.f;
    for (int i = tid; i < Kp; i += 256) s += expf(Lr[i] - m);
    s = warpSum(s);
    if ((tid & 31) == 0) sh[tid >> 5] = s;
    __syncthreads();
    if (tid == 0) {
        float t = 0.f;
#pragma unroll
        for (int w = 0; w < 8; w++) t += sh[w];
        g_c[row] = m + logf(t);
    }
}

// ---------------- column max over L, exp into out ---------------------------
__global__ __launch_bounds__(256)
void col_max(const int* __restrict__ mask, float* __restrict__ out)
{
    const int b   = blockIdx.y;
    const int k   = blockIdx.x * 256 + threadIdx.x;
    const int tid = threadIdx.x;

    __shared__ float cs[Ls];
    for (int l = tid; l < Ls; l += 256)
        cs[l] = mask[b * Ls + l] ? g_c[b * Ls + l] : INFINITY;  // +inf => never wins
    __syncthreads();

    const float* base = g_logits + (size_t)b * Ls * Kp + k;
    float t = -INFINITY;
#pragma unroll 4
    for (int l = 0; l < Ls; l++)
        t = fmaxf(t, base[(size_t)l * Kp] - cs[l]);

    out[b * Kp + k] = expf(t);   // exp(-inf) = 0 handles fully-masked batch
}

// ---------------- L2 normalize each batch row of 8192 ----------------------
__global__ __launch_bounds__(256)
void l2norm(float* __restrict__ out)
{
    const int b = blockIdx.x;
    float* o = out + b * Kp;
    const int tid = threadIdx.x;
    __shared__ float sh[8];
    __shared__ float bc;

    float s = 0.f;
    for (int i = tid; i < Kp; i += 256) { float v = o[i]; s = fmaf(v, v, s); }
    s = warpSum(s);
    if ((tid & 31) == 0) sh[tid >> 5] = s;
    __syncthreads();
    if (tid == 0) {
        float t = 0.f;
#pragma unroll
        for (int w = 0; w < 8; w++) t += sh[w];
        bc = 1.0f / fmaxf(sqrtf(t), 1e-12f);
    }
    __syncthreads();
    const float sc = bc;
    for (int i = tid; i < Kp; i += 256) o[i] *= sc;
}

// ---------------- launch ----------------------------------------------------
extern "C" void kernel_launch(void* const* d_in, const int* in_sizes, int n_in,
                              void* d_out, int out_size)
{
    const float* Q    = (const float*)d_in[0];   // (32,512,768) fp32
    const float* P    = (const float*)d_in[1];   // (8192,768)  fp32
    const float* temp = (const float*)d_in[2];   // scalar fp32
    const int*   mask = (const int*)d_in[3];     // (32,512) int32
    float* out = (float*)d_out;                  // (32,8192) fp32

    dim3 gGemm(Kp / BN, M / BM);                 // 64 x 128
    gemm_logits<<<gGemm, 256>>>(Q, P, temp);
    row_stats<<<M, 256>>>();
    dim3 gCol(Kp / 256, B);                      // 32 x 32
    col_max<<<gCol, 256>>>(mask, out);
    l2norm<<<B, 256>>>(out);
}

// round 3
// speedup vs baseline: 2.4283x; 2.4283x over previous
#include <cuda_runtime.h>
#include <cuda_bf16.h>
#include <math.h>
#include <stdint.h>

// Problem shape (fixed)
#define B_  32
#define Ls  512
#define D_  768
#define Kp  8192
#define M_  (B_ * Ls)        // 16384

// ---------------- device scratch (allocation-free) -------------------------
__device__ float g_logits[(size_t)M_ * Kp];           // 512 MB fp32 logits
__device__ float g_c[M_];                             // per-row m + log(sum exp)
__device__ __nv_bfloat16 g_Qh[(size_t)M_ * D_];
__device__ __nv_bfloat16 g_Ql[(size_t)M_ * D_];
__device__ __nv_bfloat16 g_Ph[(size_t)Kp * D_];
__device__ __nv_bfloat16 g_Pl[(size_t)Kp * D_];

// ---------------- PTX helpers (sm_80-era: valid on plain sm_103) -----------
__device__ __forceinline__ uint32_t smem_u32(const void* p) {
    uint32_t a;
    asm("{ .reg .u64 t; cvta.to.shared.u64 t, %1; cvt.u32.u64 %0, t; }"
        : "=r"(a) : "l"(p));
    return a;
}
__device__ __forceinline__ void cp16(uint32_t dst, const void* src) {
    asm volatile("cp.async.cg.shared.global [%0], [%1], 16;" :: "r"(dst), "l"(src));
}
__device__ __forceinline__ void cp_commit() {
    asm volatile("cp.async.commit_group;" ::: "memory");
}
__device__ __forceinline__ void ldm_x4(uint32_t* r, uint32_t addr) {
    asm volatile("ldmatrix.sync.aligned.m8n8.x4.shared.b16 {%0,%1,%2,%3}, [%4];"
                 : "=r"(r[0]), "=r"(r[1]), "=r"(r[2]), "=r"(r[3]) : "r"(addr));
}
__device__ __forceinline__ void mma16816(float* c, const uint32_t* a, const uint32_t* b) {
    asm volatile(
        "mma.sync.aligned.m16n8k16.row.col.f32.bf16.bf16.f32 "
        "{%0,%1,%2,%3}, {%4,%5,%6,%7}, {%8,%9}, {%0,%1,%2,%3};"
        : "+f"(c[0]), "+f"(c[1]), "+f"(c[2]), "+f"(c[3])
        : "r"(a[0]), "r"(a[1]), "r"(a[2]), "r"(a[3]), "r"(b[0]), "r"(b[1]));
}

// ---------------- split fp32 -> bf16 hi/lo ----------------------------------
__global__ __launch_bounds__(256)
void split_kernel(const float* __restrict__ src, __nv_bfloat16* __restrict__ hi,
                  __nv_bfloat16* __restrict__ lo, int n)
{
    int i = blockIdx.x * 256 + threadIdx.x;
    if (i < n) {
        float v = src[i];
        __nv_bfloat16 h = __float2bfloat16(v);
        hi[i] = h;
        lo[i] = __float2bfloat16(v - __bfloat162float(h));
    }
}

// ---------------- HMMA GEMM: logits = (Q . P^T) / temp ---------------------
// CTA tile 128x128, K-chunk 32, 8 warps (2m x 4n), warp tile 64x32.
// bf16x3: acc += ah*bh + ah*bl + al*bh  (fp32 accumulate)
#define TILE_M 128
#define TILE_N 128
#define BK     32
#define CHUNKS (D_ / BK)       // 24
#define RSTRIDE 40             // bf16 elems per smem row (80 B: pad, conflict-free)
#define TILE_BYTES (128 * RSTRIDE * 2)      // 10240 B per 128x32 tile
#define STAGE_BYTES (4 * TILE_BYTES)        // Ah, Al, Bh, Bl
#define SMEM_GEMM   (2 * STAGE_BYTES)       // 81920 B

__global__ __launch_bounds__(256, 2)
void gemm_mma(const float* __restrict__ temp)
{
    extern __shared__ __align__(16) char smem[];
    const uint32_t sb = smem_u32(smem);

    const int tid  = threadIdx.x;
    const int wid  = tid >> 5, lane = tid & 31;
    const int wm   = wid & 1;          // 0..1  -> m slot of 64
    const int wn   = wid >> 1;         // 0..3  -> n slot of 32
    const int m0   = blockIdx.x * TILE_M;
    const int n0   = blockIdx.y * TILE_N;

    // ---- async tile loader: chunk c into stage (c&1) ----
    auto load_chunk = [&](int c) {
        const uint32_t stage = sb + (uint32_t)(c & 1) * STAGE_BYTES;
        const int kd0 = c * BK;
        // 4 tiles x 128 rows x 4 x 16B = 2048 cp16; 8 per thread
#pragma unroll
        for (int it = 0; it < 8; it++) {
            int i    = tid + it * 256;          // 0..2047
            int tile = i >> 9;                  // 0:Ah 1:Al 2:Bh 3:Bl
            int r    = (i >> 2) & 127;
            int q    = i & 3;
            uint32_t dst = stage + (uint32_t)tile * TILE_BYTES + r * (RSTRIDE * 2) + q * 16;
            size_t ge = (size_t)((tile < 2 ? m0 : n0) + r) * D_ + kd0 + q * 8;
            const __nv_bfloat16* src =
                tile == 0 ? g_Qh : tile == 1 ? g_Ql : tile == 2 ? g_Ph : g_Pl;
            cp16(dst, src + ge);
        }
        cp_commit();
    };

    float acc[4][4][4];
#pragma unroll
    for (int i = 0; i < 4; i++)
#pragma unroll
        for (int j = 0; j < 4; j++)
#pragma unroll
            for (int v = 0; v < 4; v++) acc[i][j][v] = 0.f;

    load_chunk(0);
    load_chunk(1);

    for (int c = 0; c < CHUNKS; c++) {
        if (c + 1 < CHUNKS)
            asm volatile("cp.async.wait_group 1;" ::: "memory");
        else
            asm volatile("cp.async.wait_group 0;" ::: "memory");
        __syncthreads();

        const uint32_t stage = sb + (uint32_t)(c & 1) * STAGE_BYTES;
        const uint32_t Ah = stage;
        const uint32_t Al = stage + TILE_BYTES;
        const uint32_t Bh = stage + 2 * TILE_BYTES;
        const uint32_t Bl = stage + 3 * TILE_BYTES;

#pragma unroll
        for (int k16 = 0; k16 < BK; k16 += 16) {
            // ---- B fragments: 4 n-tiles of 8, hi and lo ----
            // x4 address: row = nbase + (g>>1)*8 + (lane&7), colB = (k16 + (g&1)*8)*2, g=lane>>3
            uint32_t boff = (uint32_t)((wn * 32 + ((lane >> 4) << 3) + (lane & 7)) * (RSTRIDE * 2)
                                       + (k16 + (((lane >> 3) & 1) << 3)) * 2);
            uint32_t bh[8], bl[8];
            ldm_x4(&bh[0], Bh + boff);                                   // n-tiles 0,1
            ldm_x4(&bh[4], Bh + boff + 16 * (RSTRIDE * 2));              // n-tiles 2,3
            ldm_x4(&bl[0], Bl + boff);
            ldm_x4(&bl[4], Bl + boff + 16 * (RSTRIDE * 2));

            // x4 A address: row = mbase + lane%16, colB = (k16 + (lane>>4)*8)*2
            uint32_t aoff = (uint32_t)((wm * 64 + (lane & 15)) * (RSTRIDE * 2)
                                       + (k16 + ((lane >> 4) << 3)) * 2);
#pragma unroll
            for (int mt = 0; mt < 4; mt++) {
                uint32_t ah[4], al[4];
                ldm_x4(ah, Ah + aoff + mt * 16 * (RSTRIDE * 2));
                ldm_x4(al, Al + aoff + mt * 16 * (RSTRIDE * 2));
#pragma unroll
                for (int nt = 0; nt < 4; nt++) {
                    mma16816(acc[mt][nt], ah, &bh[nt * 2]);
                    mma16816(acc[mt][nt], ah, &bl[nt * 2]);
                    mma16816(acc[mt][nt], al, &bh[nt * 2]);
                }
            }
        }
        __syncthreads();
        if (c + 2 < CHUNKS) load_chunk(c + 2);
    }

    // ---- epilogue: regs -> g_logits with 1/temp ----
    const float invT = 1.0f / temp[0];
    const int rbase = m0 + wm * 64 + (lane >> 2);
    const int cbase = n0 + wn * 32 + (lane & 3) * 2;
#pragma unroll
    for (int mt = 0; mt < 4; mt++) {
#pragma unroll
        for (int nt = 0; nt < 4; nt++) {
            float* p0 = &g_logits[(size_t)(rbase + mt * 16) * Kp + cbase + nt * 8];
            float* p1 = &g_logits[(size_t)(rbase + mt * 16 + 8) * Kp + cbase + nt * 8];
            float2 w0 = make_float2(acc[mt][nt][0] * invT, acc[mt][nt][1] * invT);
            float2 w1 = make_float2(acc[mt][nt][2] * invT, acc[mt][nt][3] * invT);
            *reinterpret_cast<float2*>(p0) = w0;
            *reinterpret_cast<float2*>(p1) = w1;
        }
    }
}

// ---------------- reductions -------------------------------------------------
__device__ __forceinline__ float warpMax(float v) {
#pragma unroll
    for (int o = 16; o; o >>= 1) v = fmaxf(v, __shfl_xor_sync(0xffffffffu, v, o));
    return v;
}
__device__ __forceinline__ float warpSum(float v) {
#pragma unroll
    for (int o = 16; o; o >>= 1) v += __shfl_xor_sync(0xffffffffu, v, o);
    return v;
}

__global__ __launch_bounds__(256)
void row_stats()
{
    const int row = blockIdx.x;
    const float* Lr = g_logits + (size_t)row * Kp;
    const int tid = threadIdx.x;
    __shared__ float sh[8];
    __shared__ float bc;

    float m = -INFINITY;
    for (int i = tid; i < Kp; i += 256) m = fmaxf(m, Lr[i]);
    m = warpMax(m);
    if ((tid & 31) == 0) sh[tid >> 5] = m;
    __syncthreads();
    if (tid == 0) {
        float t = sh[0];
#pragma unroll
        for (int w = 1; w < 8; w++) t = fmaxf(t, sh[w]);
        bc = t;
    }
    __syncthreads();
    m = bc;

    float s = 0.f;
    for (int i = tid; i < Kp; i += 256) s += expf(Lr[i] - m);
    s = warpSum(s);
    if ((tid & 31) == 0) sh[tid >> 5] = s;
    __syncthreads();
    if (tid == 0) {
        float t = 0.f;
#pragma unroll
        for (int w = 0; w < 8; w++) t += sh[w];
        g_c[row] = m + logf(t);
    }
}

__global__ __launch_bounds__(256)
void col_max(const int* __restrict__ mask, float* __restrict__ out)
{
    const int b   = blockIdx.y;
    const int k   = blockIdx.x * 256 + threadIdx.x;
    const int tid = threadIdx.x;

    __shared__ float cs[Ls];
    for (int l = tid; l < Ls; l += 256)
        cs[l] = mask[b * Ls + l] ? g_c[b * Ls + l] : INFINITY;
    __syncthreads();

    const float* base = g_logits + (size_t)b * Ls * Kp + k;
    float t = -INFINITY;
#pragma unroll 4
    for (int l = 0; l < Ls; l++)
        t = fmaxf(t, base[(size_t)l * Kp] - cs[l]);

    out[b * Kp + k] = expf(t);
}

__global__ __launch_bounds__(256)
void l2norm(float* __restrict__ out)
{
    const int b = blockIdx.x;
    float* o = out + b * Kp;
    const int tid = threadIdx.x;
    __shared__ float sh[8];
    __shared__ float bc;

    float s = 0.f;
    for (int i = tid; i < Kp; i += 256) { float v = o[i]; s = fmaf(v, v, s); }
    s = warpSum(s);
    if ((tid & 31) == 0) sh[tid >> 5] = s;
    __syncthreads();
    if (tid == 0) {
        float t = 0.f;
#pragma unroll
        for (int w = 0; w < 8; w++) t += sh[w];
        bc = 1.0f / fmaxf(sqrtf(t), 1e-12f);
    }
    __syncthreads();
    const float sc = bc;
    for (int i = tid; i < Kp; i += 256) o[i] *= sc;
}

// ---------------- launch ----------------------------------------------------
extern "C" void kernel_launch(void* const* d_in, const int* in_sizes, int n_in,
                              void* d_out, int out_size)
{
    const float* Q    = (const float*)d_in[0];   // (32,512,768)
    const float* P    = (const float*)d_in[1];   // (8192,768)
    const float* temp = (const float*)d_in[2];
    const int*   mask = (const int*)d_in[3];     // (32,512)
    float* out = (float*)d_out;                  // (32,8192)

    cudaFuncSetAttribute(gemm_mma, cudaFuncAttributeMaxDynamicSharedMemorySize,
                         SMEM_GEMM);

    __nv_bfloat16 *qh, *ql, *ph, *pl;
    cudaGetSymbolAddress((void**)&qh, g_Qh);
    cudaGetSymbolAddress((void**)&ql, g_Ql);
    cudaGetSymbolAddress((void**)&ph, g_Ph);
    cudaGetSymbolAddress((void**)&pl, g_Pl);

    const int nQ = M_ * D_, nP = Kp * D_;
    split_kernel<<<(nQ + 255) / 256, 256>>>(Q, qh, ql, nQ);
    split_kernel<<<(nP + 255) / 256, 256>>>(P, ph, pl, nP);

    dim3 gGemm(M_ / TILE_M, Kp / TILE_N);        // (128, 64)
    gemm_mma<<<gGemm, 256, SMEM_GEMM>>>(temp);

    row_stats<<<M_, 256>>>();
    dim3 gCol(Kp / 256, B_);
    col_max<<<gCol, 256>>>(mask, out);
    l2norm<<<B_, 256>>>(out);
}